// round 5
// baseline (speedup 1.0000x reference)
#include <cuda_runtime.h>
#include <math.h>

// Problem constants
#define BATCH 2
#define SEQ   2048
#define DMODEL 1024
#define NHEAD 16
#define HDIM  64
#define MTOT  (BATCH*SEQ)   // 4096

// Scratch (device globals: allocation-free per harness rules)
__device__ float g_q[BATCH*NHEAD*SEQ*HDIM];   // [b*H+h][s][d]
__device__ float g_k[BATCH*NHEAD*SEQ*HDIM];
__device__ float g_v[BATCH*NHEAD*SEQ*HDIM];
__device__ float g_ctx[BATCH*SEQ*DMODEL];     // [b][s][h*64+d]

// ----------------------------------------------------------------------------
// QKV GEMM: qkv[m,n] = sum_k x[m,k] * Wqkv[n,k]
// M=4096, N=3072, K=1024. BM=BN=64, BK=16, 256 threads, 4x4 per thread.
// Epilogue scatters into g_q/g_k/g_v in head-major layout.
// ----------------------------------------------------------------------------
__global__ __launch_bounds__(256) void qkv_gemm(const float* __restrict__ A,
                                                const float* __restrict__ W)
{
    __shared__ float As[16][68];   // [k][m], padded
    __shared__ float Ws[16][68];   // [k][n], padded

    const int tid = threadIdx.x;
    const int tx = tid & 15, ty = tid >> 4;
    const int m0 = blockIdx.x * 64;
    const int n0 = blockIdx.y * 64;
    const int lr = tid >> 2;          // 0..63
    const int lc = (tid & 3) << 2;    // 0,4,8,12

    float acc[4][4] = {};
    const float* Ag = A + (m0 + lr) * 1024 + lc;
    const float* Wg = W + (n0 + lr) * 1024 + lc;

    for (int k0 = 0; k0 < 1024; k0 += 16) {
        float4 a = *(const float4*)(Ag + k0);
        float4 w = *(const float4*)(Wg + k0);
        As[lc+0][lr]=a.x; As[lc+1][lr]=a.y; As[lc+2][lr]=a.z; As[lc+3][lr]=a.w;
        Ws[lc+0][lr]=w.x; Ws[lc+1][lr]=w.y; Ws[lc+2][lr]=w.z; Ws[lc+3][lr]=w.w;
        __syncthreads();
        #pragma unroll
        for (int k = 0; k < 16; k++) {
            float4 ra = *(const float4*)&As[k][ty*4];
            float4 rw = *(const float4*)&Ws[k][tx*4];
            float av[4] = {ra.x, ra.y, ra.z, ra.w};
            float wv[4] = {rw.x, rw.y, rw.z, rw.w};
            #pragma unroll
            for (int i = 0; i < 4; i++)
                #pragma unroll
                for (int j = 0; j < 4; j++)
                    acc[i][j] = fmaf(av[i], wv[j], acc[i][j]);
        }
        __syncthreads();
    }

    // Scatter: whole 64-wide N-tile lies in one (q/k/v, head) pair.
    const int t    = n0 >> 10;          // 0=q 1=k 2=v
    const int head = (n0 & 1023) >> 6;
    float* dst = (t == 0) ? g_q : (t == 1) ? g_k : g_v;
    #pragma unroll
    for (int i = 0; i < 4; i++) {
        int m  = m0 + ty*4 + i;
        int bb = m >> 11;      // /2048
        int ss = m & 2047;
        float4 o = make_float4(acc[i][0], acc[i][1], acc[i][2], acc[i][3]);
        *(float4*)&dst[(((bb*NHEAD + head)*SEQ + ss)*HDIM) + tx*4] = o;
    }
}

// ----------------------------------------------------------------------------
// Causal flash attention, fp32. One block = 64 query rows of one (b,h).
// smem: Qs[k][r], KPs (K as [k][c], then reused for P as [r][c]), Vs[k][d].
// 3 * 64*64*4 = 48 KB static smem. 256 threads, 4x4 microtile.
// NOTE: each 64x64 tile is 4096 floats = 16 floats per thread -> the loads
// loop over 4 column chunks (lc + {0,16,32,48}).
// ----------------------------------------------------------------------------
__global__ __launch_bounds__(256) void attn_kernel()
{
    __shared__ float Qs[64][64];    // [dim][qrow]
    __shared__ float KPs[64][64];   // phase 1: K [dim][kcol]; phase 2: P [qrow][kcol]
    __shared__ float Vs[64][64];    // [krow][dim]

    const int tid = threadIdx.x;
    const int tx = tid & 15, ty = tid >> 4;
    const int qt = blockIdx.x;      // query tile 0..31
    const int bh = blockIdx.y;      // 0..31  (b*16 + head)

    const float* Qg = g_q + ((long)bh*SEQ + qt*64)*HDIM;
    const float* Kg = g_k + (long)bh*SEQ*HDIM;
    const float* Vg = g_v + (long)bh*SEQ*HDIM;

    const int lr = tid >> 2;          // row 0..63
    const int lc = (tid & 3) << 2;    // base col 0,4,8,12

    // load Q tile transposed ([dim][row]) — full 64 dims per row
    #pragma unroll
    for (int c = 0; c < 64; c += 16) {
        float4 q4 = *(const float4*)(Qg + lr*HDIM + lc + c);
        Qs[lc+c+0][lr]=q4.x; Qs[lc+c+1][lr]=q4.y;
        Qs[lc+c+2][lr]=q4.z; Qs[lc+c+3][lr]=q4.w;
    }

    float acc[4][4] = {};
    float mrow[4], lrow[4];
    #pragma unroll
    for (int i = 0; i < 4; i++) { mrow[i] = -1e30f; lrow[i] = 0.f; }

    for (int kt = 0; kt <= qt; kt++) {
        __syncthreads();  // prior P@V reads done (and Q store visible on iter 0)
        #pragma unroll
        for (int c = 0; c < 64; c += 16) {
            float4 k4 = *(const float4*)(Kg + (kt*64 + lr)*HDIM + lc + c);
            KPs[lc+c+0][lr]=k4.x; KPs[lc+c+1][lr]=k4.y;
            KPs[lc+c+2][lr]=k4.z; KPs[lc+c+3][lr]=k4.w;
            float4 v4 = *(const float4*)(Vg + (kt*64 + lr)*HDIM + lc + c);
            *(float4*)&Vs[lr][lc+c] = v4;
        }
        __syncthreads();

        // S[i][j] = sum_k Q[r][k] * K[c][k],  r=4ty+i, c=4tx+j
        float s[4][4] = {};
        #pragma unroll 8
        for (int k = 0; k < 64; k++) {
            float4 rq = *(const float4*)&Qs[k][ty*4];
            float4 rk = *(const float4*)&KPs[k][tx*4];
            float qv[4] = {rq.x, rq.y, rq.z, rq.w};
            float kv[4] = {rk.x, rk.y, rk.z, rk.w};
            #pragma unroll
            for (int i = 0; i < 4; i++)
                #pragma unroll
                for (int j = 0; j < 4; j++)
                    s[i][j] = fmaf(qv[i], kv[j], s[i][j]);
        }

        if (kt == qt) {  // causal mask inside diagonal tile
            #pragma unroll
            for (int i = 0; i < 4; i++)
                #pragma unroll
                for (int j = 0; j < 4; j++)
                    if (tx*4 + j > ty*4 + i) s[i][j] = -1e30f;
        }

        __syncthreads();  // all K reads done before P overwrites KPs

        // online softmax per row; write P into KPs as [row][col]
        #pragma unroll
        for (int i = 0; i < 4; i++) {
            float mt = fmaxf(fmaxf(s[i][0], s[i][1]), fmaxf(s[i][2], s[i][3]));
            #pragma unroll
            for (int off = 8; off > 0; off >>= 1)
                mt = fmaxf(mt, __shfl_xor_sync(0xffffffffu, mt, off, 16));
            float mnew  = fmaxf(mrow[i], mt);
            float scale = __expf(mrow[i] - mnew);
            float p0 = __expf(s[i][0] - mnew);
            float p1 = __expf(s[i][1] - mnew);
            float p2 = __expf(s[i][2] - mnew);
            float p3 = __expf(s[i][3] - mnew);
            float psum = p0 + p1 + p2 + p3;
            #pragma unroll
            for (int off = 8; off > 0; off >>= 1)
                psum += __shfl_xor_sync(0xffffffffu, psum, off, 16);
            lrow[i] = lrow[i]*scale + psum;
            mrow[i] = mnew;
            acc[i][0] *= scale; acc[i][1] *= scale;
            acc[i][2] *= scale; acc[i][3] *= scale;
            *(float4*)&KPs[ty*4 + i][tx*4] = make_float4(p0, p1, p2, p3);
        }
        __syncthreads();

        // acc[i][j] += sum_kk P[r][kk] * V[kk][d],  d=4tx+j
        #pragma unroll 4
        for (int kk = 0; kk < 64; kk += 4) {
            float4 v0 = *(const float4*)&Vs[kk+0][tx*4];
            float4 v1 = *(const float4*)&Vs[kk+1][tx*4];
            float4 v2 = *(const float4*)&Vs[kk+2][tx*4];
            float4 v3 = *(const float4*)&Vs[kk+3][tx*4];
            #pragma unroll
            for (int i = 0; i < 4; i++) {
                float4 p4 = *(const float4*)&KPs[ty*4 + i][kk];
                acc[i][0] = fmaf(p4.x, v0.x, acc[i][0]);
                acc[i][1] = fmaf(p4.x, v0.y, acc[i][1]);
                acc[i][2] = fmaf(p4.x, v0.z, acc[i][2]);
                acc[i][3] = fmaf(p4.x, v0.w, acc[i][3]);
                acc[i][0] = fmaf(p4.y, v1.x, acc[i][0]);
                acc[i][1] = fmaf(p4.y, v1.y, acc[i][1]);
                acc[i][2] = fmaf(p4.y, v1.z, acc[i][2]);
                acc[i][3] = fmaf(p4.y, v1.w, acc[i][3]);
                acc[i][0] = fmaf(p4.z, v2.x, acc[i][0]);
                acc[i][1] = fmaf(p4.z, v2.y, acc[i][1]);
                acc[i][2] = fmaf(p4.z, v2.z, acc[i][2]);
                acc[i][3] = fmaf(p4.z, v2.w, acc[i][3]);
                acc[i][0] = fmaf(p4.w, v3.x, acc[i][0]);
                acc[i][1] = fmaf(p4.w, v3.y, acc[i][1]);
                acc[i][2] = fmaf(p4.w, v3.z, acc[i][2]);
                acc[i][3] = fmaf(p4.w, v3.w, acc[i][3]);
            }
        }
    }

    // normalize + write ctx in [b][s][h*64+d] layout
    const int bb   = bh >> 4;
    const int head = bh & 15;
    #pragma unroll
    for (int i = 0; i < 4; i++) {
        float inv = 1.f / lrow[i];
        int srow = qt*64 + ty*4 + i;
        float4 o = make_float4(acc[i][0]*inv, acc[i][1]*inv,
                               acc[i][2]*inv, acc[i][3]*inv);
        *(float4*)&g_ctx[((long)bb*SEQ + srow)*DMODEL + head*HDIM + tx*4] = o;
    }
}

// ----------------------------------------------------------------------------
// Output GEMM: out[m,p] = sum_o ctx[m,o]*Wout[p,o] + b[p].  M=4096, N=1024.
// ----------------------------------------------------------------------------
__global__ __launch_bounds__(256) void out_gemm(const float* __restrict__ W,
                                                const float* __restrict__ bias,
                                                float* __restrict__ C)
{
    __shared__ float As[16][68];
    __shared__ float Ws[16][68];

    const int tid = threadIdx.x;
    const int tx = tid & 15, ty = tid >> 4;
    const int m0 = blockIdx.x * 64;
    const int n0 = blockIdx.y * 64;
    const int lr = tid >> 2;
    const int lc = (tid & 3) << 2;

    float acc[4][4] = {};
    const float* Ag = g_ctx + (long)(m0 + lr) * 1024 + lc;
    const float* Wg = W + (long)(n0 + lr) * 1024 + lc;

    for (int k0 = 0; k0 < 1024; k0 += 16) {
        float4 a = *(const float4*)(Ag + k0);
        float4 w = *(const float4*)(Wg + k0);
        As[lc+0][lr]=a.x; As[lc+1][lr]=a.y; As[lc+2][lr]=a.z; As[lc+3][lr]=a.w;
        Ws[lc+0][lr]=w.x; Ws[lc+1][lr]=w.y; Ws[lc+2][lr]=w.z; Ws[lc+3][lr]=w.w;
        __syncthreads();
        #pragma unroll
        for (int k = 0; k < 16; k++) {
            float4 ra = *(const float4*)&As[k][ty*4];
            float4 rw = *(const float4*)&Ws[k][tx*4];
            float av[4] = {ra.x, ra.y, ra.z, ra.w};
            float wv[4] = {rw.x, rw.y, rw.z, rw.w};
            #pragma unroll
            for (int i = 0; i < 4; i++)
                #pragma unroll
                for (int j = 0; j < 4; j++)
                    acc[i][j] = fmaf(av[i], wv[j], acc[i][j]);
        }
        __syncthreads();
    }

    float4 bv = *(const float4*)&bias[n0 + tx*4];
    #pragma unroll
    for (int i = 0; i < 4; i++) {
        int m = m0 + ty*4 + i;
        float4 o = make_float4(acc[i][0] + bv.x, acc[i][1] + bv.y,
                               acc[i][2] + bv.z, acc[i][3] + bv.w);
        *(float4*)&C[(long)m*1024 + n0 + tx*4] = o;
    }
}

// ----------------------------------------------------------------------------
extern "C" void kernel_launch(void* const* d_in, const int* in_sizes, int n_in,
                              void* d_out, int out_size)
{
    const float* x    = (const float*)d_in[0];   // [2,2048,1024]
    const float* Wqkv = (const float*)d_in[1];   // [3072,1024]
    const float* Wout = (const float*)d_in[2];   // [1024,1024]
    const float* bout = (const float*)d_in[3];   // [1024]
    float* out = (float*)d_out;                  // [2,2048,1024]

    qkv_gemm<<<dim3(MTOT/64, 3*DMODEL/64), 256>>>(x, Wqkv);
    attn_kernel<<<dim3(SEQ/64, BATCH*NHEAD), 256>>>();
    out_gemm<<<dim3(MTOT/64, DMODEL/64), 256>>>(Wout, bout, out);
}

// round 8
// speedup vs baseline: 1.4327x; 1.4327x over previous
#include <cuda_runtime.h>
#include <cuda_bf16.h>
#include <math.h>
#include <stdint.h>

// Problem constants
#define BATCH 2
#define SEQ   2048
#define DMODEL 1024
#define NHEAD 16
#define HDIM  64
#define MTOT  (BATCH*SEQ)   // 4096

// Scratch (device globals: allocation-free per harness rules)
__device__ float g_q[BATCH*NHEAD*SEQ*HDIM];   // [b*H+h][s][d]
__device__ float g_k[BATCH*NHEAD*SEQ*HDIM];
__device__ float g_v[BATCH*NHEAD*SEQ*HDIM];
__device__ float g_ctx[BATCH*SEQ*DMODEL];     // [b][s][h*64+d]

// ----------------------------------------------------------------------------
// bf16x3 helpers: split fp32 into hi (bf16) + lo (bf16 of residual).
// hi·hi + hi·lo + lo·hi in fp32 accum -> ~1e-5 relative accuracy.
// ----------------------------------------------------------------------------
__device__ __forceinline__ uint32_t pack_split(float x, float y, uint32_t& lo_pack)
{
    uint32_t h;
    // cvt.rn.bf16x2.f32 d, a, b : a -> high half, b -> low half
    asm("cvt.rn.bf16x2.f32 %0, %1, %2;" : "=r"(h) : "f"(y), "f"(x));
    float hx = __uint_as_float(h << 16);            // low-half bf16 as fp32
    float hy = __uint_as_float(h & 0xffff0000u);    // high-half bf16 as fp32
    asm("cvt.rn.bf16x2.f32 %0, %1, %2;" : "=r"(lo_pack) : "f"(y - hy), "f"(x - hx));
    return h;
}

#define MMA_BF16(d, a, b)                                                   \
    asm volatile("mma.sync.aligned.m16n8k16.row.col.f32.bf16.bf16.f32 "     \
                 "{%0,%1,%2,%3}, {%4,%5,%6,%7}, {%8,%9}, {%0,%1,%2,%3};"    \
                 : "+f"((d)[0]), "+f"((d)[1]), "+f"((d)[2]), "+f"((d)[3])   \
                 : "r"((a)[0]), "r"((a)[1]), "r"((a)[2]), "r"((a)[3]),      \
                   "r"((b)[0]), "r"((b)[1]))

// ----------------------------------------------------------------------------
// Shared GEMM core: C[128 x 64] tile of  A[m,k] * W[n,k]^T, K=1024.
// 256 threads = 8 warps as 4(M) x 2(N); each warp 32x32; thread 2x4 mma tiles.
// Smem rows padded to 20 u32 (40 bf16, 80B stride) -> conflict-free frags.
// EPILOGUE macro-style via a flag: 0 = qkv scatter, 1 = out + bias.
// ----------------------------------------------------------------------------
struct Frag { float acc[2][4][4]; };

template <int EPI>
__device__ __forceinline__ void gemm_bf16x3(const float* __restrict__ A,
                                            const float* __restrict__ W,
                                            const float* __restrict__ bias,
                                            float* __restrict__ C)
{
    __shared__ uint32_t Ah[128][20], Al[128][20];
    __shared__ uint32_t Wh[64][20],  Wl[64][20];

    const int tid   = threadIdx.x;
    const int lane  = tid & 31;
    const int warp  = tid >> 5;
    const int g     = lane >> 2;      // 0..7
    const int q     = lane & 3;       // 0..3
    const int warpM = warp >> 1;      // 0..3
    const int warpN = warp & 1;       // 0..1

    const int m0 = blockIdx.x * 128;
    const int n0 = blockIdx.y * 64;

    // loader mapping: A: row=tid/2, 16 floats starting at (tid&1)*16
    //                 W: row=tid/4, 8 floats starting at (tid&3)*8
    const int ar  = tid >> 1;
    const int acb = (tid & 1) * 16;           // float col base
    const int wr  = tid >> 2;
    const int wcb = (tid & 3) * 8;

    const float* Ap = A + (long)(m0 + ar) * 1024 + acb;
    const float* Wp = W + (long)(n0 + wr) * 1024 + wcb;

    float4 a4[4], w4[2];

    // initial prefetch (k0 = 0)
    #pragma unroll
    for (int i = 0; i < 4; i++) a4[i] = *(const float4*)(Ap + 4*i);
    #pragma unroll
    for (int i = 0; i < 2; i++) w4[i] = *(const float4*)(Wp + 4*i);

    float acc[2][4][4] = {};

    for (int k0 = 0; k0 < 1024; k0 += 32) {
        // store staged regs -> smem (split hi/lo, pack pairs)
        #pragma unroll
        for (int i = 0; i < 4; i++) {
            uint32_t l01, l23;
            uint32_t h01 = pack_split(a4[i].x, a4[i].y, l01);
            uint32_t h23 = pack_split(a4[i].z, a4[i].w, l23);
            int cc = (acb >> 1) + 2*i;
            Ah[ar][cc]   = h01; Ah[ar][cc+1] = h23;
            Al[ar][cc]   = l01; Al[ar][cc+1] = l23;
        }
        #pragma unroll
        for (int i = 0; i < 2; i++) {
            uint32_t l01, l23;
            uint32_t h01 = pack_split(w4[i].x, w4[i].y, l01);
            uint32_t h23 = pack_split(w4[i].z, w4[i].w, l23);
            int cc = (wcb >> 1) + 2*i;
            Wh[wr][cc]   = h01; Wh[wr][cc+1] = h23;
            Wl[wr][cc]   = l01; Wl[wr][cc+1] = l23;
        }
        __syncthreads();

        // prefetch next stage
        if (k0 + 32 < 1024) {
            #pragma unroll
            for (int i = 0; i < 4; i++) a4[i] = *(const float4*)(Ap + k0 + 32 + 4*i);
            #pragma unroll
            for (int i = 0; i < 2; i++) w4[i] = *(const float4*)(Wp + k0 + 32 + 4*i);
        }

        // compute: 2 k-steps of 16
        #pragma unroll
        for (int ks = 0; ks < 2; ks++) {
            const int kb = ks*8 + q;
            uint32_t afh[2][4], afl[2][4];
            #pragma unroll
            for (int mi = 0; mi < 2; mi++) {
                int r = warpM*32 + mi*16;
                afh[mi][0] = Ah[r+g][kb];     afh[mi][1] = Ah[r+g+8][kb];
                afh[mi][2] = Ah[r+g][kb+4];   afh[mi][3] = Ah[r+g+8][kb+4];
                afl[mi][0] = Al[r+g][kb];     afl[mi][1] = Al[r+g+8][kb];
                afl[mi][2] = Al[r+g][kb+4];   afl[mi][3] = Al[r+g+8][kb+4];
            }
            uint32_t bfh[4][2], bfl[4][2];
            #pragma unroll
            for (int ni = 0; ni < 4; ni++) {
                int n = warpN*32 + ni*8 + g;
                bfh[ni][0] = Wh[n][kb]; bfh[ni][1] = Wh[n][kb+4];
                bfl[ni][0] = Wl[n][kb]; bfl[ni][1] = Wl[n][kb+4];
            }
            #pragma unroll
            for (int mi = 0; mi < 2; mi++)
                #pragma unroll
                for (int ni = 0; ni < 4; ni++) {
                    MMA_BF16(acc[mi][ni], afh[mi], bfh[ni]);
                    MMA_BF16(acc[mi][ni], afh[mi], bfl[ni]);
                    MMA_BF16(acc[mi][ni], afl[mi], bfh[ni]);
                }
        }
        __syncthreads();
    }

    // ---------------- epilogue ----------------
    if (EPI == 0) {
        // scatter to g_q/g_k/g_v head-major
        const int t    = n0 >> 10;
        const int head = (n0 & 1023) >> 6;
        float* dst = (t == 0) ? g_q : (t == 1) ? g_k : g_v;
        #pragma unroll
        for (int mi = 0; mi < 2; mi++) {
            #pragma unroll
            for (int half = 0; half < 2; half++) {
                int m  = m0 + warpM*32 + mi*16 + g + half*8;
                int bb = m >> 11;
                int ss = m & 2047;
                float* drow = dst + (((long)(bb*NHEAD + head)*SEQ + ss) * HDIM);
                #pragma unroll
                for (int ni = 0; ni < 4; ni++) {
                    int col = warpN*32 + ni*8 + q*2;
                    float2 o = half ? make_float2(acc[mi][ni][2], acc[mi][ni][3])
                                    : make_float2(acc[mi][ni][0], acc[mi][ni][1]);
                    *(float2*)(drow + col) = o;
                }
            }
        }
    } else {
        #pragma unroll
        for (int mi = 0; mi < 2; mi++) {
            #pragma unroll
            for (int half = 0; half < 2; half++) {
                int m = m0 + warpM*32 + mi*16 + g + half*8;
                float* crow = C + (long)m*1024 + n0;
                #pragma unroll
                for (int ni = 0; ni < 4; ni++) {
                    int col = warpN*32 + ni*8 + q*2;
                    float2 bv = *(const float2*)(bias + n0 + col);
                    float2 o = half ? make_float2(acc[mi][ni][2] + bv.x, acc[mi][ni][3] + bv.y)
                                    : make_float2(acc[mi][ni][0] + bv.x, acc[mi][ni][1] + bv.y);
                    *(float2*)(crow + col) = o;
                }
            }
        }
    }
}

__global__ __launch_bounds__(256) void qkv_gemm_mma(const float* __restrict__ A,
                                                    const float* __restrict__ W)
{
    gemm_bf16x3<0>(A, W, nullptr, nullptr);
}

__global__ __launch_bounds__(256) void out_gemm_mma(const float* __restrict__ W,
                                                    const float* __restrict__ bias,
                                                    float* __restrict__ C)
{
    gemm_bf16x3<1>(g_ctx, W, bias, C);
}

// ----------------------------------------------------------------------------
// Causal flash attention, fp32 (unchanged from R5 passing version).
// ----------------------------------------------------------------------------
__global__ __launch_bounds__(256) void attn_kernel()
{
    __shared__ float Qs[64][64];    // [dim][qrow]
    __shared__ float KPs[64][64];   // phase 1: K [dim][kcol]; phase 2: P [qrow][kcol]
    __shared__ float Vs[64][64];    // [krow][dim]

    const int tid = threadIdx.x;
    const int tx = tid & 15, ty = tid >> 4;
    const int qt = blockIdx.x;      // query tile 0..31
    const int bh = blockIdx.y;      // 0..31  (b*16 + head)

    const float* Qg = g_q + ((long)bh*SEQ + qt*64)*HDIM;
    const float* Kg = g_k + (long)bh*SEQ*HDIM;
    const float* Vg = g_v + (long)bh*SEQ*HDIM;

    const int lr = tid >> 2;          // row 0..63
    const int lc = (tid & 3) << 2;    // base col 0,4,8,12

    #pragma unroll
    for (int c = 0; c < 64; c += 16) {
        float4 q4 = *(const float4*)(Qg + lr*HDIM + lc + c);
        Qs[lc+c+0][lr]=q4.x; Qs[lc+c+1][lr]=q4.y;
        Qs[lc+c+2][lr]=q4.z; Qs[lc+c+3][lr]=q4.w;
    }

    float acc[4][4] = {};
    float mrow[4], lrow[4];
    #pragma unroll
    for (int i = 0; i < 4; i++) { mrow[i] = -1e30f; lrow[i] = 0.f; }

    for (int kt = 0; kt <= qt; kt++) {
        __syncthreads();
        #pragma unroll
        for (int c = 0; c < 64; c += 16) {
            float4 k4 = *(const float4*)(Kg + (kt*64 + lr)*HDIM + lc + c);
            KPs[lc+c+0][lr]=k4.x; KPs[lc+c+1][lr]=k4.y;
            KPs[lc+c+2][lr]=k4.z; KPs[lc+c+3][lr]=k4.w;
            float4 v4 = *(const float4*)(Vg + (kt*64 + lr)*HDIM + lc + c);
            *(float4*)&Vs[lr][lc+c] = v4;
        }
        __syncthreads();

        float s[4][4] = {};
        #pragma unroll 8
        for (int k = 0; k < 64; k++) {
            float4 rq = *(const float4*)&Qs[k][ty*4];
            float4 rk = *(const float4*)&KPs[k][tx*4];
            float qv[4] = {rq.x, rq.y, rq.z, rq.w};
            float kv[4] = {rk.x, rk.y, rk.z, rk.w};
            #pragma unroll
            for (int i = 0; i < 4; i++)
                #pragma unroll
                for (int j = 0; j < 4; j++)
                    s[i][j] = fmaf(qv[i], kv[j], s[i][j]);
        }

        if (kt == qt) {
            #pragma unroll
            for (int i = 0; i < 4; i++)
                #pragma unroll
                for (int j = 0; j < 4; j++)
                    if (tx*4 + j > ty*4 + i) s[i][j] = -1e30f;
        }

        __syncthreads();

        #pragma unroll
        for (int i = 0; i < 4; i++) {
            float mt = fmaxf(fmaxf(s[i][0], s[i][1]), fmaxf(s[i][2], s[i][3]));
            #pragma unroll
            for (int off = 8; off > 0; off >>= 1)
                mt = fmaxf(mt, __shfl_xor_sync(0xffffffffu, mt, off, 16));
            float mnew  = fmaxf(mrow[i], mt);
            float scale = __expf(mrow[i] - mnew);
            float p0 = __expf(s[i][0] - mnew);
            float p1 = __expf(s[i][1] - mnew);
            float p2 = __expf(s[i][2] - mnew);
            float p3 = __expf(s[i][3] - mnew);
            float psum = p0 + p1 + p2 + p3;
            #pragma unroll
            for (int off = 8; off > 0; off >>= 1)
                psum += __shfl_xor_sync(0xffffffffu, psum, off, 16);
            lrow[i] = lrow[i]*scale + psum;
            mrow[i] = mnew;
            acc[i][0] *= scale; acc[i][1] *= scale;
            acc[i][2] *= scale; acc[i][3] *= scale;
            *(float4*)&KPs[ty*4 + i][tx*4] = make_float4(p0, p1, p2, p3);
        }
        __syncthreads();

        #pragma unroll 4
        for (int kk = 0; kk < 64; kk += 4) {
            float4 v0 = *(const float4*)&Vs[kk+0][tx*4];
            float4 v1 = *(const float4*)&Vs[kk+1][tx*4];
            float4 v2 = *(const float4*)&Vs[kk+2][tx*4];
            float4 v3 = *(const float4*)&Vs[kk+3][tx*4];
            #pragma unroll
            for (int i = 0; i < 4; i++) {
                float4 p4 = *(const float4*)&KPs[ty*4 + i][kk];
                acc[i][0] = fmaf(p4.x, v0.x, acc[i][0]);
                acc[i][1] = fmaf(p4.x, v0.y, acc[i][1]);
                acc[i][2] = fmaf(p4.x, v0.z, acc[i][2]);
                acc[i][3] = fmaf(p4.x, v0.w, acc[i][3]);
                acc[i][0] = fmaf(p4.y, v1.x, acc[i][0]);
                acc[i][1] = fmaf(p4.y, v1.y, acc[i][1]);
                acc[i][2] = fmaf(p4.y, v1.z, acc[i][2]);
                acc[i][3] = fmaf(p4.y, v1.w, acc[i][3]);
                acc[i][0] = fmaf(p4.z, v2.x, acc[i][0]);
                acc[i][1] = fmaf(p4.z, v2.y, acc[i][1]);
                acc[i][2] = fmaf(p4.z, v2.z, acc[i][2]);
                acc[i][3] = fmaf(p4.z, v2.w, acc[i][3]);
                acc[i][0] = fmaf(p4.w, v3.x, acc[i][0]);
                acc[i][1] = fmaf(p4.w, v3.y, acc[i][1]);
                acc[i][2] = fmaf(p4.w, v3.z, acc[i][2]);
                acc[i][3] = fmaf(p4.w, v3.w, acc[i][3]);
            }
        }
    }

    const int bb   = bh >> 4;
    const int head = bh & 15;
    #pragma unroll
    for (int i = 0; i < 4; i++) {
        float inv = 1.f / lrow[i];
        int srow = qt*64 + ty*4 + i;
        float4 o = make_float4(acc[i][0]*inv, acc[i][1]*inv,
                               acc[i][2]*inv, acc[i][3]*inv);
        *(float4*)&g_ctx[((long)bb*SEQ + srow)*DMODEL + head*HDIM + tx*4] = o;
    }
}

// ----------------------------------------------------------------------------
extern "C" void kernel_launch(void* const* d_in, const int* in_sizes, int n_in,
                              void* d_out, int out_size)
{
    const float* x    = (const float*)d_in[0];   // [2,2048,1024]
    const float* Wqkv = (const float*)d_in[1];   // [3072,1024]
    const float* Wout = (const float*)d_in[2];   // [1024,1024]
    const float* bout = (const float*)d_in[3];   // [1024]
    float* out = (float*)d_out;                  // [2,2048,1024]

    qkv_gemm_mma<<<dim3(MTOT/128, 3*DMODEL/64), 256>>>(x, Wqkv);
    attn_kernel<<<dim3(SEQ/64, BATCH*NHEAD), 256>>>();
    out_gemm_mma<<<dim3(MTOT/128, DMODEL/64), 256>>>(Wout, bout, out);
}

// round 9
// speedup vs baseline: 2.2711x; 1.5852x over previous
#include <cuda_runtime.h>
#include <cuda_bf16.h>
#include <math.h>
#include <stdint.h>

// Problem constants
#define BATCH 2
#define SEQ   2048
#define DMODEL 1024
#define NHEAD 16
#define HDIM  64
#define MTOT  (BATCH*SEQ)   // 4096
#define NBH   (BATCH*NHEAD) // 32

// Scratch (device globals: allocation-free per harness rules)
// Q/K pre-split bf16 hi/lo: [bh][s][64]
__device__ unsigned short g_qh[NBH*SEQ*HDIM], g_ql[NBH*SEQ*HDIM];
__device__ unsigned short g_kh[NBH*SEQ*HDIM], g_kl[NBH*SEQ*HDIM];
// V pre-split + transposed: [bh][d][s]
__device__ unsigned short g_vth[NBH*HDIM*SEQ], g_vtl[NBH*HDIM*SEQ];
__device__ float g_ctx[MTOT*DMODEL];     // [b][s][h*64+d]

// ----------------------------------------------------------------------------
// bf16x3 helpers
// ----------------------------------------------------------------------------
__device__ __forceinline__ uint32_t pack_split(float x, float y, uint32_t& lo_pack)
{
    uint32_t h;
    // cvt.rn.bf16x2.f32 d, a, b : a -> high half, b -> low half
    asm("cvt.rn.bf16x2.f32 %0, %1, %2;" : "=r"(h) : "f"(y), "f"(x));
    float hx = __uint_as_float(h << 16);
    float hy = __uint_as_float(h & 0xffff0000u);
    asm("cvt.rn.bf16x2.f32 %0, %1, %2;" : "=r"(lo_pack) : "f"(y - hy), "f"(x - hx));
    return h;
}

#define MMA_BF16(d, a, b)                                                   \
    asm volatile("mma.sync.aligned.m16n8k16.row.col.f32.bf16.bf16.f32 "     \
                 "{%0,%1,%2,%3}, {%4,%5,%6,%7}, {%8,%9}, {%0,%1,%2,%3};"    \
                 : "+f"((d)[0]), "+f"((d)[1]), "+f"((d)[2]), "+f"((d)[3])   \
                 : "r"((a)[0]), "r"((a)[1]), "r"((a)[2]), "r"((a)[3]),      \
                   "r"((b)[0]), "r"((b)[1]))

// ----------------------------------------------------------------------------
// GEMM core (as R8): C[128x64] of A[m,k]*W[n,k]^T, K=1024, bf16x3.
// EPI 0: qkv epilogue -> split bf16 hi/lo scatter (Q,K row-major; V transposed)
// EPI 1: out + bias (fp32)
// ----------------------------------------------------------------------------
template <int EPI>
__device__ __forceinline__ void gemm_bf16x3(const float* __restrict__ A,
                                            const float* __restrict__ W,
                                            const float* __restrict__ bias,
                                            float* __restrict__ C)
{
    __shared__ uint32_t Ah[128][20], Al[128][20];
    __shared__ uint32_t Wh[64][20],  Wl[64][20];

    const int tid   = threadIdx.x;
    const int lane  = tid & 31;
    const int warp  = tid >> 5;
    const int g     = lane >> 2;
    const int q     = lane & 3;
    const int warpM = warp >> 1;
    const int warpN = warp & 1;

    const int m0 = blockIdx.x * 128;
    const int n0 = blockIdx.y * 64;

    const int ar  = tid >> 1;
    const int acb = (tid & 1) * 16;
    const int wr  = tid >> 2;
    const int wcb = (tid & 3) * 8;

    const float* Ap = A + (long)(m0 + ar) * 1024 + acb;
    const float* Wp = W + (long)(n0 + wr) * 1024 + wcb;

    float4 a4[4], w4[2];
    #pragma unroll
    for (int i = 0; i < 4; i++) a4[i] = *(const float4*)(Ap + 4*i);
    #pragma unroll
    for (int i = 0; i < 2; i++) w4[i] = *(const float4*)(Wp + 4*i);

    float acc[2][4][4] = {};

    for (int k0 = 0; k0 < 1024; k0 += 32) {
        #pragma unroll
        for (int i = 0; i < 4; i++) {
            uint32_t l01, l23;
            uint32_t h01 = pack_split(a4[i].x, a4[i].y, l01);
            uint32_t h23 = pack_split(a4[i].z, a4[i].w, l23);
            int cc = (acb >> 1) + 2*i;
            Ah[ar][cc]   = h01; Ah[ar][cc+1] = h23;
            Al[ar][cc]   = l01; Al[ar][cc+1] = l23;
        }
        #pragma unroll
        for (int i = 0; i < 2; i++) {
            uint32_t l01, l23;
            uint32_t h01 = pack_split(w4[i].x, w4[i].y, l01);
            uint32_t h23 = pack_split(w4[i].z, w4[i].w, l23);
            int cc = (wcb >> 1) + 2*i;
            Wh[wr][cc]   = h01; Wh[wr][cc+1] = h23;
            Wl[wr][cc]   = l01; Wl[wr][cc+1] = l23;
        }
        __syncthreads();

        if (k0 + 32 < 1024) {
            #pragma unroll
            for (int i = 0; i < 4; i++) a4[i] = *(const float4*)(Ap + k0 + 32 + 4*i);
            #pragma unroll
            for (int i = 0; i < 2; i++) w4[i] = *(const float4*)(Wp + k0 + 32 + 4*i);
        }

        #pragma unroll
        for (int ks = 0; ks < 2; ks++) {
            const int kb = ks*8 + q;
            uint32_t afh[2][4], afl[2][4];
            #pragma unroll
            for (int mi = 0; mi < 2; mi++) {
                int r = warpM*32 + mi*16;
                afh[mi][0] = Ah[r+g][kb];     afh[mi][1] = Ah[r+g+8][kb];
                afh[mi][2] = Ah[r+g][kb+4];   afh[mi][3] = Ah[r+g+8][kb+4];
                afl[mi][0] = Al[r+g][kb];     afl[mi][1] = Al[r+g+8][kb];
                afl[mi][2] = Al[r+g][kb+4];   afl[mi][3] = Al[r+g+8][kb+4];
            }
            uint32_t bfh[4][2], bfl[4][2];
            #pragma unroll
            for (int ni = 0; ni < 4; ni++) {
                int n = warpN*32 + ni*8 + g;
                bfh[ni][0] = Wh[n][kb]; bfh[ni][1] = Wh[n][kb+4];
                bfl[ni][0] = Wl[n][kb]; bfl[ni][1] = Wl[n][kb+4];
            }
            #pragma unroll
            for (int mi = 0; mi < 2; mi++)
                #pragma unroll
                for (int ni = 0; ni < 4; ni++) {
                    MMA_BF16(acc[mi][ni], afh[mi], bfh[ni]);
                    MMA_BF16(acc[mi][ni], afh[mi], bfl[ni]);
                    MMA_BF16(acc[mi][ni], afl[mi], bfh[ni]);
                }
        }
        __syncthreads();
    }

    if (EPI == 0) {
        const int t    = n0 >> 10;          // 0=q 1=k 2=v
        const int head = (n0 & 1023) >> 6;
        #pragma unroll
        for (int mi = 0; mi < 2; mi++) {
            #pragma unroll
            for (int half = 0; half < 2; half++) {
                int m  = m0 + warpM*32 + mi*16 + g + half*8;
                int bb = m >> 11;
                int ss = m & 2047;
                int bh = bb*NHEAD + head;
                #pragma unroll
                for (int ni = 0; ni < 4; ni++) {
                    int col = warpN*32 + ni*8 + q*2;   // 0..63 within head
                    float v0 = half ? acc[mi][ni][2] : acc[mi][ni][0];
                    float v1 = half ? acc[mi][ni][3] : acc[mi][ni][1];
                    uint32_t lo;
                    uint32_t hi = pack_split(v0, v1, lo);
                    if (t == 0) {
                        long idx = ((long)bh*SEQ + ss)*HDIM + col;
                        *(uint32_t*)&g_qh[idx] = hi;
                        *(uint32_t*)&g_ql[idx] = lo;
                    } else if (t == 1) {
                        long idx = ((long)bh*SEQ + ss)*HDIM + col;
                        *(uint32_t*)&g_kh[idx] = hi;
                        *(uint32_t*)&g_kl[idx] = lo;
                    } else {
                        long base = (long)bh*HDIM*SEQ;
                        g_vth[base + (long)col*SEQ + ss]     = (unsigned short)(hi & 0xffffu);
                        g_vth[base + (long)(col+1)*SEQ + ss] = (unsigned short)(hi >> 16);
                        g_vtl[base + (long)col*SEQ + ss]     = (unsigned short)(lo & 0xffffu);
                        g_vtl[base + (long)(col+1)*SEQ + ss] = (unsigned short)(lo >> 16);
                    }
                }
            }
        }
    } else {
        #pragma unroll
        for (int mi = 0; mi < 2; mi++) {
            #pragma unroll
            for (int half = 0; half < 2; half++) {
                int m = m0 + warpM*32 + mi*16 + g + half*8;
                float* crow = C + (long)m*1024 + n0;
                #pragma unroll
                for (int ni = 0; ni < 4; ni++) {
                    int col = warpN*32 + ni*8 + q*2;
                    float2 bv = *(const float2*)(bias + n0 + col);
                    float2 o = half ? make_float2(acc[mi][ni][2] + bv.x, acc[mi][ni][3] + bv.y)
                                    : make_float2(acc[mi][ni][0] + bv.x, acc[mi][ni][1] + bv.y);
                    *(float2*)(crow + col) = o;
                }
            }
        }
    }
}

__global__ __launch_bounds__(256) void qkv_gemm_mma(const float* __restrict__ A,
                                                    const float* __restrict__ W)
{
    gemm_bf16x3<0>(A, W, nullptr, nullptr);
}

__global__ __launch_bounds__(256) void out_gemm_mma(const float* __restrict__ W,
                                                    const float* __restrict__ bias,
                                                    float* __restrict__ C)
{
    gemm_bf16x3<1>(g_ctx, W, bias, C);
}

// ----------------------------------------------------------------------------
// MMA flash attention (bf16x3). Block = 128 q rows of one (b,h), 8 warps x m16.
// S in c-frag regs -> softmax in-register -> P re-split to bf16 hi/lo fed
// directly as A-frags of the P*V mma. K/V tiles in smem, stride 36 u32
// (bank = 4g+q -> conflict-free fragment loads).
// ----------------------------------------------------------------------------
__global__ __launch_bounds__(256, 1) void attn_mma()
{
    __shared__ uint32_t Kh[64][36], Kl[64][36], Vh[64][36], Vl[64][36];

    const int tid  = threadIdx.x;
    const int lane = tid & 31;
    const int warp = tid >> 5;
    const int g = lane >> 2;
    const int q = lane & 3;
    const int qt = blockIdx.x;          // 0..15 (128 rows each)
    const int bh = blockIdx.y;          // 0..31
    const int row0 = qt*128 + warp*16;  // warp's first q row

    // Q a-frags hi/lo for 4 k-steps (head dim 64)
    uint32_t qfh[4][4], qfl[4][4];
    {
        const uint32_t* q0h = (const uint32_t*)&g_qh[((long)bh*SEQ + row0)*HDIM];
        const uint32_t* q0l = (const uint32_t*)&g_ql[((long)bh*SEQ + row0)*HDIM];
        #pragma unroll
        for (int ks = 0; ks < 4; ks++) {
            qfh[ks][0] = q0h[g*32 + ks*8 + q];
            qfh[ks][1] = q0h[(g+8)*32 + ks*8 + q];
            qfh[ks][2] = q0h[g*32 + ks*8 + q + 4];
            qfh[ks][3] = q0h[(g+8)*32 + ks*8 + q + 4];
            qfl[ks][0] = q0l[g*32 + ks*8 + q];
            qfl[ks][1] = q0l[(g+8)*32 + ks*8 + q];
            qfl[ks][2] = q0l[g*32 + ks*8 + q + 4];
            qfl[ks][3] = q0l[(g+8)*32 + ks*8 + q + 4];
        }
    }

    float oacc[8][4] = {};
    float mrow0 = -1e30f, mrow1 = -1e30f;
    float lrow0 = 0.f,    lrow1 = 0.f;

    const int ld_r = tid >> 2;          // 0..63
    const int ld_c = (tid & 3) * 8;     // u32 col base
    const int u4i  = (tid & 3) * 2;     // uint4 index

    const int ktmax = 2*qt + 1;
    for (int kt = 0; kt <= ktmax; kt++) {
        __syncthreads();   // previous tile's smem reads done
        {
            long koff = ((long)bh*SEQ + kt*64 + ld_r)*HDIM;
            const uint4* kh4 = (const uint4*)&g_kh[koff];
            const uint4* kl4 = (const uint4*)&g_kl[koff];
            long voff = ((long)bh*HDIM + ld_r)*SEQ + kt*64;
            const uint4* vh4 = (const uint4*)&g_vth[voff];
            const uint4* vl4 = (const uint4*)&g_vtl[voff];
            *(uint4*)&Kh[ld_r][ld_c]   = kh4[u4i];
            *(uint4*)&Kh[ld_r][ld_c+4] = kh4[u4i+1];
            *(uint4*)&Kl[ld_r][ld_c]   = kl4[u4i];
            *(uint4*)&Kl[ld_r][ld_c+4] = kl4[u4i+1];
            *(uint4*)&Vh[ld_r][ld_c]   = vh4[u4i];
            *(uint4*)&Vh[ld_r][ld_c+4] = vh4[u4i+1];
            *(uint4*)&Vl[ld_r][ld_c]   = vl4[u4i];
            *(uint4*)&Vl[ld_r][ld_c+4] = vl4[u4i+1];
        }
        __syncthreads();

        // warp-uniform activity: any unmasked element in this tile?
        if (row0 + 15 < kt*64) continue;

        // ---- S = Q K^T (bf16x3) ----
        float s[8][4] = {};
        #pragma unroll
        for (int nt = 0; nt < 8; nt++) {
            const int n = nt*8 + g;
            #pragma unroll
            for (int ks = 0; ks < 4; ks++) {
                uint32_t bhv[2] = { Kh[n][ks*8+q], Kh[n][ks*8+q+4] };
                uint32_t blv[2] = { Kl[n][ks*8+q], Kl[n][ks*8+q+4] };
                MMA_BF16(s[nt], qfh[ks], bhv);
                MMA_BF16(s[nt], qfh[ks], blv);
                MMA_BF16(s[nt], qfl[ks], bhv);
            }
        }

        // ---- causal mask (edge tiles only) ----
        if (kt*64 + 63 > row0) {
            #pragma unroll
            for (int nt = 0; nt < 8; nt++) {
                int c0 = kt*64 + nt*8 + 2*q;
                int r0r = row0 + g;
                int r1r = row0 + g + 8;
                if (c0     > r0r) s[nt][0] = -1e30f;
                if (c0 + 1 > r0r) s[nt][1] = -1e30f;
                if (c0     > r1r) s[nt][2] = -1e30f;
                if (c0 + 1 > r1r) s[nt][3] = -1e30f;
            }
        }

        // ---- online softmax (rows g and g+8; quad shfl reductions) ----
        float mx0 = -1e30f, mx1 = -1e30f;
        #pragma unroll
        for (int nt = 0; nt < 8; nt++) {
            mx0 = fmaxf(mx0, fmaxf(s[nt][0], s[nt][1]));
            mx1 = fmaxf(mx1, fmaxf(s[nt][2], s[nt][3]));
        }
        mx0 = fmaxf(mx0, __shfl_xor_sync(0xffffffffu, mx0, 1));
        mx0 = fmaxf(mx0, __shfl_xor_sync(0xffffffffu, mx0, 2));
        mx1 = fmaxf(mx1, __shfl_xor_sync(0xffffffffu, mx1, 1));
        mx1 = fmaxf(mx1, __shfl_xor_sync(0xffffffffu, mx1, 2));

        float mn0 = fmaxf(mrow0, mx0);
        float mn1 = fmaxf(mrow1, mx1);
        float sc0 = __expf(mrow0 - mn0);
        float sc1 = __expf(mrow1 - mn1);
        mrow0 = mn0; mrow1 = mn1;

        float sum0 = 0.f, sum1 = 0.f;
        #pragma unroll
        for (int nt = 0; nt < 8; nt++) {
            s[nt][0] = __expf(s[nt][0] - mn0);
            s[nt][1] = __expf(s[nt][1] - mn0);
            s[nt][2] = __expf(s[nt][2] - mn1);
            s[nt][3] = __expf(s[nt][3] - mn1);
            sum0 += s[nt][0] + s[nt][1];
            sum1 += s[nt][2] + s[nt][3];
        }
        sum0 += __shfl_xor_sync(0xffffffffu, sum0, 1);
        sum0 += __shfl_xor_sync(0xffffffffu, sum0, 2);
        sum1 += __shfl_xor_sync(0xffffffffu, sum1, 1);
        sum1 += __shfl_xor_sync(0xffffffffu, sum1, 2);
        lrow0 = lrow0*sc0 + sum0;
        lrow1 = lrow1*sc1 + sum1;

        #pragma unroll
        for (int dt = 0; dt < 8; dt++) {
            oacc[dt][0] *= sc0; oacc[dt][1] *= sc0;
            oacc[dt][2] *= sc1; oacc[dt][3] *= sc1;
        }

        // ---- pack P into bf16 hi/lo (c-frag -> a-frag layout identity) ----
        uint32_t ph[8][2], pl[8][2];
        #pragma unroll
        for (int nt = 0; nt < 8; nt++) {
            ph[nt][0] = pack_split(s[nt][0], s[nt][1], pl[nt][0]);
            ph[nt][1] = pack_split(s[nt][2], s[nt][3], pl[nt][1]);
        }

        // ---- O += P V (bf16x3) ----
        #pragma unroll
        for (int ks2 = 0; ks2 < 4; ks2++) {
            uint32_t afh[4] = { ph[2*ks2][0], ph[2*ks2][1], ph[2*ks2+1][0], ph[2*ks2+1][1] };
            uint32_t afl[4] = { pl[2*ks2][0], pl[2*ks2][1], pl[2*ks2+1][0], pl[2*ks2+1][1] };
            #pragma unroll
            for (int dt = 0; dt < 8; dt++) {
                const int n = dt*8 + g;
                uint32_t bhv[2] = { Vh[n][ks2*8+q], Vh[n][ks2*8+q+4] };
                uint32_t blv[2] = { Vl[n][ks2*8+q], Vl[n][ks2*8+q+4] };
                MMA_BF16(oacc[dt], afh, bhv);
                MMA_BF16(oacc[dt], afh, blv);
                MMA_BF16(oacc[dt], afl, bhv);
            }
        }
    }

    // ---- epilogue: normalize + write ctx [b][s][h*64+d] ----
    const float i0 = 1.f / lrow0;
    const float i1 = 1.f / lrow1;
    const int bb   = bh >> 4;
    const int head = bh & 15;
    #pragma unroll
    for (int dt = 0; dt < 8; dt++) {
        int col = head*64 + dt*8 + q*2;
        long r0 = (long)bb*SEQ + row0 + g;
        long r1 = r0 + 8;
        *(float2*)&g_ctx[r0*DMODEL + col] = make_float2(oacc[dt][0]*i0, oacc[dt][1]*i0);
        *(float2*)&g_ctx[r1*DMODEL + col] = make_float2(oacc[dt][2]*i1, oacc[dt][3]*i1);
    }
}

// ----------------------------------------------------------------------------
extern "C" void kernel_launch(void* const* d_in, const int* in_sizes, int n_in,
                              void* d_out, int out_size)
{
    const float* x    = (const float*)d_in[0];   // [2,2048,1024]
    const float* Wqkv = (const float*)d_in[1];   // [3072,1024]
    const float* Wout = (const float*)d_in[2];   // [1024,1024]
    const float* bout = (const float*)d_in[3];   // [1024]
    float* out = (float*)d_out;                  // [2,2048,1024]

    qkv_gemm_mma<<<dim3(MTOT/128, 3*DMODEL/64), 256>>>(x, Wqkv);
    attn_mma<<<dim3(SEQ/128, NBH), 256>>>();
    out_gemm_mma<<<dim3(MTOT/128, DMODEL/64), 256>>>(Wout, bout, out);
}

// round 11
// speedup vs baseline: 2.4876x; 1.0953x over previous
#include <cuda_runtime.h>
#include <cuda_bf16.h>
#include <math.h>
#include <stdint.h>

// Problem constants
#define BATCH 2
#define SEQ   2048
#define DMODEL 1024
#define NHEAD 16
#define HDIM  64
#define MTOT  (BATCH*SEQ)   // 4096
#define NBH   (BATCH*NHEAD) // 32

// Scratch (device globals: allocation-free per harness rules)
__device__ unsigned short g_qh[NBH*SEQ*HDIM], g_ql[NBH*SEQ*HDIM];
__device__ unsigned short g_kh[NBH*SEQ*HDIM], g_kl[NBH*SEQ*HDIM];
__device__ unsigned short g_vth[NBH*HDIM*SEQ], g_vtl[NBH*HDIM*SEQ]; // [bh][d][s]
__device__ float g_ctx[MTOT*DMODEL];     // [b][s][h*64+d]

// ----------------------------------------------------------------------------
// helpers
// ----------------------------------------------------------------------------
__device__ __forceinline__ uint32_t pack_split(float x, float y, uint32_t& lo_pack)
{
    uint32_t h;
    asm("cvt.rn.bf16x2.f32 %0, %1, %2;" : "=r"(h) : "f"(y), "f"(x));
    float hx = __uint_as_float(h << 16);
    float hy = __uint_as_float(h & 0xffff0000u);
    asm("cvt.rn.bf16x2.f32 %0, %1, %2;" : "=r"(lo_pack) : "f"(y - hy), "f"(x - hx));
    return h;
}

__device__ __forceinline__ uint32_t smem_u32(const void* p)
{
    return (uint32_t)__cvta_generic_to_shared(p);
}

#define MMA_BF16(d, a, b)                                                   \
    asm volatile("mma.sync.aligned.m16n8k16.row.col.f32.bf16.bf16.f32 "     \
                 "{%0,%1,%2,%3}, {%4,%5,%6,%7}, {%8,%9}, {%0,%1,%2,%3};"    \
                 : "+f"((d)[0]), "+f"((d)[1]), "+f"((d)[2]), "+f"((d)[3])   \
                 : "r"((a)[0]), "r"((a)[1]), "r"((a)[2]), "r"((a)[3]),      \
                   "r"((b)[0]), "r"((b)[1]))

#define LDSM_X4(r0, r1, r2, r3, addr)                                        \
    asm volatile("ldmatrix.sync.aligned.m8n8.x4.shared.b16 {%0,%1,%2,%3}, [%4];" \
                 : "=r"(r0), "=r"(r1), "=r"(r2), "=r"(r3) : "r"(addr))

// ----------------------------------------------------------------------------
// GEMM core: C[128x64] of A[m,k]*W[n,k]^T, K=1024, bf16x3, LDSM fragments.
// EPI 0: qkv epilogue -> split bf16 hi/lo scatter; EPI 1: out + bias.
// ----------------------------------------------------------------------------
template <int EPI>
__device__ __forceinline__ void gemm_bf16x3(const float* __restrict__ A,
                                            const float* __restrict__ W,
                                            const float* __restrict__ bias,
                                            float* __restrict__ C)
{
    __shared__ __align__(16) uint32_t Ah[128][20], Al[128][20];
    __shared__ __align__(16) uint32_t Wh[64][20],  Wl[64][20];

    const int tid   = threadIdx.x;
    const int lane  = tid & 31;
    const int warp  = tid >> 5;
    const int g     = lane >> 2;
    const int q     = lane & 3;
    const int warpM = warp >> 1;
    const int warpN = warp & 1;

    const int m0 = blockIdx.x * 128;
    const int n0 = blockIdx.y * 64;

    const int ar  = tid >> 1;
    const int acb = (tid & 1) * 16;
    const int wr  = tid >> 2;
    const int wcb = (tid & 3) * 8;

    const float* Ap = A + (long)(m0 + ar) * 1024 + acb;
    const float* Wp = W + (long)(n0 + wr) * 1024 + wcb;

    // LDSM lane addresses (constant offsets within tiles)
    const int a_row = lane & 15;              // + base row
    const int a_chk = (lane >> 4) << 2;       // + ks*8
    const int b_rof = ((lane >> 4) << 3) + (lane & 7);
    const int b_chk = ((lane >> 3) & 1) << 2;

    float4 a4[4], w4[2];
    #pragma unroll
    for (int i = 0; i < 4; i++) a4[i] = *(const float4*)(Ap + 4*i);
    #pragma unroll
    for (int i = 0; i < 2; i++) w4[i] = *(const float4*)(Wp + 4*i);

    float acc[2][4][4] = {};

    for (int k0 = 0; k0 < 1024; k0 += 32) {
        #pragma unroll
        for (int i = 0; i < 4; i++) {
            uint32_t l01, l23;
            uint32_t h01 = pack_split(a4[i].x, a4[i].y, l01);
            uint32_t h23 = pack_split(a4[i].z, a4[i].w, l23);
            int cc = (acb >> 1) + 2*i;
            Ah[ar][cc]   = h01; Ah[ar][cc+1] = h23;
            Al[ar][cc]   = l01; Al[ar][cc+1] = l23;
        }
        #pragma unroll
        for (int i = 0; i < 2; i++) {
            uint32_t l01, l23;
            uint32_t h01 = pack_split(w4[i].x, w4[i].y, l01);
            uint32_t h23 = pack_split(w4[i].z, w4[i].w, l23);
            int cc = (wcb >> 1) + 2*i;
            Wh[wr][cc]   = h01; Wh[wr][cc+1] = h23;
            Wl[wr][cc]   = l01; Wl[wr][cc+1] = l23;
        }
        __syncthreads();

        if (k0 + 32 < 1024) {
            #pragma unroll
            for (int i = 0; i < 4; i++) a4[i] = *(const float4*)(Ap + k0 + 32 + 4*i);
            #pragma unroll
            for (int i = 0; i < 2; i++) w4[i] = *(const float4*)(Wp + k0 + 32 + 4*i);
        }

        #pragma unroll
        for (int ks = 0; ks < 2; ks++) {
            const int kc = ks*8;
            uint32_t afh[2][4], afl[2][4];
            #pragma unroll
            for (int mi = 0; mi < 2; mi++) {
                const int r = warpM*32 + mi*16;
                LDSM_X4(afh[mi][0], afh[mi][1], afh[mi][2], afh[mi][3],
                        smem_u32(&Ah[r + a_row][kc + a_chk]));
                LDSM_X4(afl[mi][0], afl[mi][1], afl[mi][2], afl[mi][3],
                        smem_u32(&Al[r + a_row][kc + a_chk]));
            }
            uint32_t bfh[4][2], bfl[4][2];
            #pragma unroll
            for (int p = 0; p < 2; p++) {
                const int nb = warpN*32 + p*16;
                LDSM_X4(bfh[2*p][0], bfh[2*p][1], bfh[2*p+1][0], bfh[2*p+1][1],
                        smem_u32(&Wh[nb + b_rof][kc + b_chk]));
                LDSM_X4(bfl[2*p][0], bfl[2*p][1], bfl[2*p+1][0], bfl[2*p+1][1],
                        smem_u32(&Wl[nb + b_rof][kc + b_chk]));
            }
            #pragma unroll
            for (int mi = 0; mi < 2; mi++)
                #pragma unroll
                for (int ni = 0; ni < 4; ni++) {
                    MMA_BF16(acc[mi][ni], afh[mi], bfh[ni]);
                    MMA_BF16(acc[mi][ni], afh[mi], bfl[ni]);
                    MMA_BF16(acc[mi][ni], afl[mi], bfh[ni]);
                }
        }
        __syncthreads();
    }

    if (EPI == 0) {
        const int t    = n0 >> 10;          // 0=q 1=k 2=v
        const int head = (n0 & 1023) >> 6;
        #pragma unroll
        for (int mi = 0; mi < 2; mi++) {
            #pragma unroll
            for (int half = 0; half < 2; half++) {
                int m  = m0 + warpM*32 + mi*16 + g + half*8;
                int bb = m >> 11;
                int ss = m & 2047;
                int bh = bb*NHEAD + head;
                #pragma unroll
                for (int ni = 0; ni < 4; ni++) {
                    int col = warpN*32 + ni*8 + q*2;
                    float v0 = half ? acc[mi][ni][2] : acc[mi][ni][0];
                    float v1 = half ? acc[mi][ni][3] : acc[mi][ni][1];
                    uint32_t lo;
                    uint32_t hi = pack_split(v0, v1, lo);
                    if (t == 0) {
                        long idx = ((long)bh*SEQ + ss)*HDIM + col;
                        *(uint32_t*)&g_qh[idx] = hi;
                        *(uint32_t*)&g_ql[idx] = lo;
                    } else if (t == 1) {
                        long idx = ((long)bh*SEQ + ss)*HDIM + col;
                        *(uint32_t*)&g_kh[idx] = hi;
                        *(uint32_t*)&g_kl[idx] = lo;
                    } else {
                        long base = (long)bh*HDIM*SEQ;
                        g_vth[base + (long)col*SEQ + ss]     = (unsigned short)(hi & 0xffffu);
                        g_vth[base + (long)(col+1)*SEQ + ss] = (unsigned short)(hi >> 16);
                        g_vtl[base + (long)col*SEQ + ss]     = (unsigned short)(lo & 0xffffu);
                        g_vtl[base + (long)(col+1)*SEQ + ss] = (unsigned short)(lo >> 16);
                    }
                }
            }
        }
    } else {
        #pragma unroll
        for (int mi = 0; mi < 2; mi++) {
            #pragma unroll
            for (int half = 0; half < 2; half++) {
                int m = m0 + warpM*32 + mi*16 + g + half*8;
                float* crow = C + (long)m*1024 + n0;
                #pragma unroll
                for (int ni = 0; ni < 4; ni++) {
                    int col = warpN*32 + ni*8 + q*2;
                    float2 bv = *(const float2*)(bias + n0 + col);
                    float2 o = half ? make_float2(acc[mi][ni][2] + bv.x, acc[mi][ni][3] + bv.y)
                                    : make_float2(acc[mi][ni][0] + bv.x, acc[mi][ni][1] + bv.y);
                    *(float2*)(crow + col) = o;
                }
            }
        }
    }
}

__global__ __launch_bounds__(256) void qkv_gemm_mma(const float* __restrict__ A,
                                                    const float* __restrict__ W)
{
    gemm_bf16x3<0>(A, W, nullptr, nullptr);
}

__global__ __launch_bounds__(256) void out_gemm_mma(const float* __restrict__ W,
                                                    const float* __restrict__ bias,
                                                    float* __restrict__ C)
{
    gemm_bf16x3<1>(g_ctx, W, bias, C);
}

// ----------------------------------------------------------------------------
// MMA flash attention (bf16x3), LDSM fragment loads.
// Block = 128 q rows of one (b,h), 8 warps x m16.
// ----------------------------------------------------------------------------
__global__ __launch_bounds__(256, 1) void attn_mma()
{
    __shared__ __align__(16) uint32_t Kh[64][36], Kl[64][36], Vh[64][36], Vl[64][36];

    const int tid  = threadIdx.x;
    const int lane = tid & 31;
    const int warp = tid >> 5;
    const int g = lane >> 2;
    const int q = lane & 3;
    const int qt = blockIdx.x;          // 0..15
    const int bh = blockIdx.y;          // 0..31
    const int row0 = qt*128 + warp*16;

    const int b_rof = ((lane >> 4) << 3) + (lane & 7);   // ldmatrix b-addr row offset
    const int b_chk = ((lane >> 3) & 1) << 2;            // + ks*8

    // Q a-frags hi/lo for 4 k-steps
    uint32_t qfh[4][4], qfl[4][4];
    {
        const uint32_t* q0h = (const uint32_t*)&g_qh[((long)bh*SEQ + row0)*HDIM];
        const uint32_t* q0l = (const uint32_t*)&g_ql[((long)bh*SEQ + row0)*HDIM];
        #pragma unroll
        for (int ks = 0; ks < 4; ks++) {
            qfh[ks][0] = q0h[g*32 + ks*8 + q];
            qfh[ks][1] = q0h[(g+8)*32 + ks*8 + q];
            qfh[ks][2] = q0h[g*32 + ks*8 + q + 4];
            qfh[ks][3] = q0h[(g+8)*32 + ks*8 + q + 4];
            qfl[ks][0] = q0l[g*32 + ks*8 + q];
            qfl[ks][1] = q0l[(g+8)*32 + ks*8 + q];
            qfl[ks][2] = q0l[g*32 + ks*8 + q + 4];
            qfl[ks][3] = q0l[(g+8)*32 + ks*8 + q + 4];
        }
    }

    float oacc[8][4] = {};
    float mrow0 = -1e30f, mrow1 = -1e30f;
    float lrow0 = 0.f,    lrow1 = 0.f;

    const int ld_r = tid >> 2;
    const int ld_c = (tid & 3) * 8;
    const int u4i  = (tid & 3) * 2;

    const int ktmax = 2*qt + 1;
    for (int kt = 0; kt <= ktmax; kt++) {
        __syncthreads();
        {
            long koff = ((long)bh*SEQ + kt*64 + ld_r)*HDIM;
            const uint4* kh4 = (const uint4*)&g_kh[koff];
            const uint4* kl4 = (const uint4*)&g_kl[koff];
            long voff = ((long)bh*HDIM + ld_r)*SEQ + kt*64;
            const uint4* vh4 = (const uint4*)&g_vth[voff];
            const uint4* vl4 = (const uint4*)&g_vtl[voff];
            *(uint4*)&Kh[ld_r][ld_c]   = kh4[u4i];
            *(uint4*)&Kh[ld_r][ld_c+4] = kh4[u4i+1];
            *(uint4*)&Kl[ld_r][ld_c]   = kl4[u4i];
            *(uint4*)&Kl[ld_r][ld_c+4] = kl4[u4i+1];
            *(uint4*)&Vh[ld_r][ld_c]   = vh4[u4i];
            *(uint4*)&Vh[ld_r][ld_c+4] = vh4[u4i+1];
            *(uint4*)&Vl[ld_r][ld_c]   = vl4[u4i];
            *(uint4*)&Vl[ld_r][ld_c+4] = vl4[u4i+1];
        }
        __syncthreads();

        if (row0 + 15 < kt*64) continue;   // fully masked for this warp

        // ---- S = Q K^T ----
        float s[8][4] = {};
        #pragma unroll
        for (int ks = 0; ks < 4; ks++) {
            const int kc = ks*8;
            #pragma unroll
            for (int p = 0; p < 4; p++) {
                const int nb = p*16;
                uint32_t bh0[2], bh1[2], bl0[2], bl1[2];
                LDSM_X4(bh0[0], bh0[1], bh1[0], bh1[1],
                        smem_u32(&Kh[nb + b_rof][kc + b_chk]));
                LDSM_X4(bl0[0], bl0[1], bl1[0], bl1[1],
                        smem_u32(&Kl[nb + b_rof][kc + b_chk]));
                MMA_BF16(s[2*p],   qfh[ks], bh0);
                MMA_BF16(s[2*p],   qfh[ks], bl0);
                MMA_BF16(s[2*p],   qfl[ks], bh0);
                MMA_BF16(s[2*p+1], qfh[ks], bh1);
                MMA_BF16(s[2*p+1], qfh[ks], bl1);
                MMA_BF16(s[2*p+1], qfl[ks], bh1);
            }
        }

        // ---- causal mask (edge tiles only) ----
        if (kt*64 + 63 > row0) {
            #pragma unroll
            for (int nt = 0; nt < 8; nt++) {
                int c0 = kt*64 + nt*8 + 2*q;
                int r0r = row0 + g;
                int r1r = row0 + g + 8;
                if (c0     > r0r) s[nt][0] = -1e30f;
                if (c0 + 1 > r0r) s[nt][1] = -1e30f;
                if (c0     > r1r) s[nt][2] = -1e30f;
                if (c0 + 1 > r1r) s[nt][3] = -1e30f;
            }
        }

        // ---- online softmax ----
        float mx0 = -1e30f, mx1 = -1e30f;
        #pragma unroll
        for (int nt = 0; nt < 8; nt++) {
            mx0 = fmaxf(mx0, fmaxf(s[nt][0], s[nt][1]));
            mx1 = fmaxf(mx1, fmaxf(s[nt][2], s[nt][3]));
        }
        mx0 = fmaxf(mx0, __shfl_xor_sync(0xffffffffu, mx0, 1));
        mx0 = fmaxf(mx0, __shfl_xor_sync(0xffffffffu, mx0, 2));
        mx1 = fmaxf(mx1, __shfl_xor_sync(0xffffffffu, mx1, 1));
        mx1 = fmaxf(mx1, __shfl_xor_sync(0xffffffffu, mx1, 2));

        float mn0 = fmaxf(mrow0, mx0);
        float mn1 = fmaxf(mrow1, mx1);
        float sc0 = __expf(mrow0 - mn0);
        float sc1 = __expf(mrow1 - mn1);
        mrow0 = mn0; mrow1 = mn1;

        float sum0 = 0.f, sum1 = 0.f;
        #pragma unroll
        for (int nt = 0; nt < 8; nt++) {
            s[nt][0] = __expf(s[nt][0] - mn0);
            s[nt][1] = __expf(s[nt][1] - mn0);
            s[nt][2] = __expf(s[nt][2] - mn1);
            s[nt][3] = __expf(s[nt][3] - mn1);
            sum0 += s[nt][0] + s[nt][1];
            sum1 += s[nt][2] + s[nt][3];
        }
        sum0 += __shfl_xor_sync(0xffffffffu, sum0, 1);
        sum0 += __shfl_xor_sync(0xffffffffu, sum0, 2);
        sum1 += __shfl_xor_sync(0xffffffffu, sum1, 1);
        sum1 += __shfl_xor_sync(0xffffffffu, sum1, 2);
        lrow0 = lrow0*sc0 + sum0;
        lrow1 = lrow1*sc1 + sum1;

        #pragma unroll
        for (int dt = 0; dt < 8; dt++) {
            oacc[dt][0] *= sc0; oacc[dt][1] *= sc0;
            oacc[dt][2] *= sc1; oacc[dt][3] *= sc1;
        }

        // ---- pack P into bf16 hi/lo ----
        uint32_t ph[8][2], pl[8][2];
        #pragma unroll
        for (int nt = 0; nt < 8; nt++) {
            ph[nt][0] = pack_split(s[nt][0], s[nt][1], pl[nt][0]);
            ph[nt][1] = pack_split(s[nt][2], s[nt][3], pl[nt][1]);
        }

        // ---- O += P V ----
        #pragma unroll
        for (int ks2 = 0; ks2 < 4; ks2++) {
            const int kc = ks2*8;
            uint32_t afh[4] = { ph[2*ks2][0], ph[2*ks2][1], ph[2*ks2+1][0], ph[2*ks2+1][1] };
            uint32_t afl[4] = { pl[2*ks2][0], pl[2*ks2][1], pl[2*ks2+1][0], pl[2*ks2+1][1] };
            #pragma unroll
            for (int p = 0; p < 4; p++) {
                const int nb = p*16;
                uint32_t bh0[2], bh1[2], bl0[2], bl1[2];
                LDSM_X4(bh0[0], bh0[1], bh1[0], bh1[1],
                        smem_u32(&Vh[nb + b_rof][kc + b_chk]));
                LDSM_X4(bl0[0], bl0[1], bl1[0], bl1[1],
                        smem_u32(&Vl[nb + b_rof][kc + b_chk]));
                MMA_BF16(oacc[2*p],   afh, bh0);
                MMA_BF16(oacc[2*p],   afh, bl0);
                MMA_BF16(oacc[2*p],   afl, bh0);
                MMA_BF16(oacc[2*p+1], afh, bh1);
                MMA_BF16(oacc[2*p+1], afh, bl1);
                MMA_BF16(oacc[2*p+1], afl, bh1);
            }
        }
    }

    // ---- epilogue ----
    const float i0 = 1.f / lrow0;
    const float i1 = 1.f / lrow1;
    const int bb   = bh >> 4;
    const int head = bh & 15;
    #pragma unroll
    for (int dt = 0; dt < 8; dt++) {
        int col = head*64 + dt*8 + q*2;
        long r0 = (long)bb*SEQ + row0 + g;
        long r1 = r0 + 8;
        *(float2*)&g_ctx[r0*DMODEL + col] = make_float2(oacc[dt][0]*i0, oacc[dt][1]*i0);
        *(float2*)&g_ctx[r1*DMODEL + col] = make_float2(oacc[dt][2]*i1, oacc[dt][3]*i1);
    }
}

// ----------------------------------------------------------------------------
extern "C" void kernel_launch(void* const* d_in, const int* in_sizes, int n_in,
                              void* d_out, int out_size)
{
    const float* x    = (const float*)d_in[0];   // [2,2048,1024]
    const float* Wqkv = (const float*)d_in[1];   // [3072,1024]
    const float* Wout = (const float*)d_in[2];   // [1024,1024]
    const float* bout = (const float*)d_in[3];   // [1024]
    float* out = (float*)d_out;                  // [2,2048,1024]

    qkv_gemm_mma<<<dim3(MTOT/128, 3*DMODEL/64), 256>>>(x, Wqkv);
    attn_mma<<<dim3(SEQ/128, NBH), 256>>>();
    out_gemm_mma<<<dim3(MTOT/128, DMODEL/64), 256>>>(Wout, bout, out);
}